// round 15
// baseline (speedup 1.0000x reference)
#include <cuda_runtime.h>
#include <cuda_bf16.h>
#include <math.h>

// HMM forward, linear domain, power-of-2 rescale, HMMA matvec (W in regs),
// DSMEM-push x exchange. 32 clusters x 4 CTAs, 2 batches/cluster.
// R14: M-fold hoisted above MMA (hidden under tensor latency); redux.sync
// warp max; own-value u16 DSMEM pushes (no shuffles); per-warp syncwarp +
// remote arrives (mbar count 32) instead of a named barrier.

#define HH 512
#define VV 50257
#define TT 512
#define NT 512
#define RPC 128
#define NCL 32

using ull = unsigned long long;
using u32 = unsigned int;

#define CLUSTER_SYNC() do { \
  asm volatile("barrier.cluster.arrive.aligned;" ::: "memory"); \
  asm volatile("barrier.cluster.wait.aligned;"   ::: "memory"); \
} while (0)

__device__ __forceinline__ u32 smem_u32(const void* p) {
  u32 a;
  asm("{ .reg .u64 t; cvta.to.shared.u64 t, %1; cvt.u32.u64 %0, t; }" : "=r"(a) : "l"(p));
  return a;
}
__device__ __forceinline__ u32 mapa_u32(u32 local, int rank) {
  u32 r;
  asm("mapa.shared::cluster.u32 %0, %1, %2;" : "=r"(r) : "r"(local), "r"(rank));
  return r;
}
__device__ __forceinline__ void mbar_wait_acq(u32 addr, u32 ph) {
  asm volatile(
    "{\n\t.reg .pred P;\n\t"
    "W%=:\n\t"
    "mbarrier.try_wait.parity.acquire.cluster.shared::cta.b64 P, [%0], %1, 0x989680;\n\t"
    "@!P bra W%=;\n\t}"
    :: "r"(addr), "r"(ph) : "memory");
}
__device__ __forceinline__ u32 pkbf(float a, float b) {
  __nv_bfloat162 t = __float22bfloat162_rn(make_float2(a, b));
  return *(u32*)&t;
}
#define MMA16816(c0, c1, c2, c3, a0, a1, a2, a3, b0, b1) \
  asm volatile( \
    "mma.sync.aligned.m16n8k16.row.col.f32.bf16.bf16.f32 " \
    "{%0,%1,%2,%3}, {%4,%5,%6,%7}, {%8,%9}, {%0,%1,%2,%3};" \
    : "+f"(c0), "+f"(c1), "+f"(c2), "+f"(c3) \
    : "r"(a0), "r"(a1), "r"(a2), "r"(a3), "r"(b0), "r"(b1))

__global__ void __cluster_dims__(4, 1, 1) __launch_bounds__(NT, 1)
hmm_main(const float* __restrict__ A, const float* __restrict__ beta,
         const float* __restrict__ gamma, const int* __restrict__ ids,
         float* __restrict__ out) {
  __shared__ __align__(16) u32    xsb[2][2][264];  // [par][b][kp] bf16x2, pad
  __shared__ __align__(16) float2 red2[2][128];    // [khalf][row] = (b0,b1)
  __shared__ float wmxp[2][4][4][2];               // [par][slice][quarter][b]
  __shared__ __align__(16) float a0s[1024];
  __shared__ int   sids[2][TT];
  __shared__ float smax2[16];
  __shared__ __align__(8) ull mbars2[2];           // per-parity, count=32

  const int tid  = threadIdx.x;
  const int myq  = blockIdx.x & 3;     // cluster rank == row-slice
  const int cl   = blockIdx.x >> 2;    // cluster id
  const int base = myq * RPC;
  const int warp = tid >> 5, lane = tid & 31;
  const int mt = warp & 7, kh = warp >> 3;   // m-tile, k-half
  const int r4 = lane >> 2, tig = lane & 3;

  // ---- prologue: W fragments into registers (persistent, 64 u32) ----
  u32 Areg[64];
  {
    const int row0 = base + mt * 16 + r4;
    #pragma unroll
    for (int kt = 0; kt < 16; kt++) {
      const int k0 = kh * 256 + kt * 16 + 2 * tig;
      const float* p0 = A + (size_t)k0 * HH;
      float w00 = p0[row0]              + 1e-12f;
      float w01 = p0[HH + row0]         + 1e-12f;
      float w10 = p0[row0 + 8]          + 1e-12f;
      float w11 = p0[HH + row0 + 8]     + 1e-12f;
      float w20 = p0[8 * HH + row0]     + 1e-12f;
      float w21 = p0[9 * HH + row0]     + 1e-12f;
      float w30 = p0[8 * HH + row0 + 8] + 1e-12f;
      float w31 = p0[9 * HH + row0 + 8] + 1e-12f;
      Areg[kt * 4 + 0] = pkbf(w00, w01);
      Areg[kt * 4 + 1] = pkbf(w10, w11);
      Areg[kt * 4 + 2] = pkbf(w20, w21);
      Areg[kt * 4 + 3] = pkbf(w30, w31);
    }
  }
  for (int i = tid; i < 2 * TT; i += NT) {
    int b0 = i >> 9, t0 = i & (TT - 1);
    sids[b0][t0] = ids[(cl * 2 + b0) * TT + t0];
  }
  if (tid < 2)
    asm volatile("mbarrier.init.shared.b64 [%0], %1;"
                 :: "r"(smem_u32(&mbars2[tid])), "r"(32u) : "memory");
  __syncthreads();

  // ---- init: alpha0 (2 batches), M0; x1 + wmxp[1] built LOCALLY ----
  float M0[2];
  {
    for (int idx = tid; idx < 2 * HH; idx += NT) {
      int bb = idx >> 9, k = idx & 511;
      a0s[idx] = __logf(gamma[k]) + __ldg(&beta[(size_t)k * VV + sids[bb][0]]);
    }
    __syncthreads();
    {
      int bb = warp >> 3, seg = warp & 7;
      float m = fmaxf(a0s[bb * 512 + seg * 64 + lane],
                      a0s[bb * 512 + seg * 64 + 32 + lane]);
      #pragma unroll
      for (int o = 16; o > 0; o >>= 1)
        m = fmaxf(m, __shfl_xor_sync(0xffffffffu, m, o));
      if (lane == 0) smax2[warp] = m;
    }
    __syncthreads();
    #pragma unroll
    for (int bb = 0; bb < 2; bb++) {
      float m = smax2[bb * 8];
      #pragma unroll
      for (int s = 1; s < 8; s++) m = fmaxf(m, smax2[bb * 8 + s]);
      M0[bb] = m;
    }
    {
      int bx = tid >> 8, kp = tid & 255;
      float v0 = __expf(a0s[bx * 512 + 2 * kp]     - M0[bx]);
      float v1 = __expf(a0s[bx * 512 + 2 * kp + 1] - M0[bx]);
      xsb[1][bx][kp] = pkbf(v0, v1);
    }
    {
      #pragma unroll
      for (int bb = 0; bb < 2; bb++) {
        float m = a0s[bb * 512 + warp * 32 + lane];
        #pragma unroll
        for (int o = 16; o > 0; o >>= 1)
          m = fmaxf(m, __shfl_xor_sync(0xffffffffu, m, o));
        if (lane == 0) wmxp[1][warp >> 2][warp & 3][bb] = __expf(m - M0[bb]);
      }
    }
    __syncthreads();
  }
  CLUSTER_SYNC();

  const bool act = (tid < 256);
  const int  b   = tid >> 7;           // batch (0/1) for act threads
  const int  r   = tid & (RPC - 1);    // row-in-slice
  const int  h   = base + r;
  const float C0 = M0[b & 1];
  int Cexp = 0;
  const u32 xsb_u  = smem_u32(xsb);
  const u32 wmxp_u = smem_u32(wmxp);
  const u32 mb0_u  = smem_u32(&mbars2[0]);
  int phs0 = 0, phs1 = 0;

  // depth-2 emission prefetch
  float e_cur = 0.0f, bq = 0.0f;
  if (act) {
    e_cur = __expf(__ldg(&beta[(size_t)h * VV + sids[b][1]]));
    bq = __ldg(&beta[(size_t)h * VV + sids[b][2]]);
  }

  for (int t = 1; t < TT; t++) {
    const int par = t & 1;

    float bnew = 0.0f;
    if (act && t + 2 < TT)
      bnew = __ldg(&beta[(size_t)h * VV + sids[b][t + 2]]);

    if (t >= 2) {
      if (par == 0) { mbar_wait_acq(mb0_u, phs0); phs0 ^= 1; }
      else          { mbar_wait_acq(mb0_u + 8, phs1); phs1 ^= 1; }
    }

    // M-fold hoisted: wmxp[par] valid post-wait; hides under MMA latency
    float invM = 0.0f;
    int ebd = 0;
    if (act) {
      float M = wmxp[par][0][0][b];
      #pragma unroll
      for (int q = 0; q < 4; q++)
        #pragma unroll
        for (int qr = 0; qr < 4; qr++)
          M = fmaxf(M, wmxp[par][q][qr][b]);
      int eb = (int)(__float_as_uint(M) >> 23);
      invM = __uint_as_float((u32)(254 - eb) << 23);
      ebd = eb - 127;
    }

    // 16 mma.sync per warp, B fragments straight from local xsb[par]
    float c0 = 0.f, c1 = 0.f, c2 = 0.f, c3 = 0.f;
    float d0 = 0.f, d1 = 0.f, d2 = 0.f, d3 = 0.f;
    {
      const int kpb = kh * 128;
      #pragma unroll
      for (int kt = 0; kt < 16; kt += 2) {
        u32 b0 = 0, b1 = 0, b2 = 0, b3 = 0;
        if (lane < 8) {
          b0 = xsb[par][r4][kpb + kt * 8 + tig];
          b1 = xsb[par][r4][kpb + kt * 8 + tig + 4];
          b2 = xsb[par][r4][kpb + kt * 8 + 8 + tig];
          b3 = xsb[par][r4][kpb + kt * 8 + 8 + tig + 4];
        }
        MMA16816(c0, c1, c2, c3,
                 Areg[kt * 4 + 0], Areg[kt * 4 + 1],
                 Areg[kt * 4 + 2], Areg[kt * 4 + 3], b0, b1);
        MMA16816(d0, d1, d2, d3,
                 Areg[kt * 4 + 4], Areg[kt * 4 + 5],
                 Areg[kt * 4 + 6], Areg[kt * 4 + 7], b2, b3);
      }
    }
    if (tig == 0) {
      red2[kh][mt * 16 + r4]     = make_float2(c0 + d0, c1 + d1);
      red2[kh][mt * 16 + r4 + 8] = make_float2(c2 + d2, c3 + d3);
    }
    __syncthreads();   // red2 complete; all reads of xsb[par] done

    if (act) {
      const float* rk0 = (const float*)&red2[0][0];
      const float* rk1 = (const float*)&red2[1][0];
      float z = rk0[r * 2 + b] + rk1[r * 2 + b];

      Cexp += ebd;
      float u = z * e_cur * invM;

      if (t == TT - 1) {
        out[(cl * 2 + b) * HH + h] =
            (float)((double)__logf(u) + (double)C0
                    + (double)Cexp * 0.6931471805599453);
      } else {
        // own-value bf16 push to all 4 CTAs (u16 DSMEM stores, no shuffle)
        unsigned short hv;
        asm("cvt.rn.bf16.f32 %0, %1;" : "=h"(hv) : "f"(u));
        u32 loff = xsb_u + (u32)((((par ^ 1) * 2 + b) * 264 + (h >> 1)) * 4
                                 + (h & 1) * 2);
        #pragma unroll
        for (int q = 0; q < 4; q++) {
          u32 ra = mapa_u32(loff, q);
          asm volatile("st.shared::cluster.u16 [%0], %1;" :: "r"(ra), "h"(hv) : "memory");
        }

        // warp max via redux (u > 0 => float max == uint max)
        u32 wmu;
        asm("redux.sync.max.u32 %0, %1, 0xffffffff;" : "=r"(wmu) : "r"(__float_as_uint(u)));
        if (lane < 4) {
          u32 woff = wmxp_u +
              (u32)(((((par ^ 1) * 4 + myq) * 4 + (warp & 3)) * 2 + b) * 4);
          u32 wra = mapa_u32(woff, lane);
          asm volatile("st.shared::cluster.u32 [%0], %1;" :: "r"(wra), "r"(wmu) : "memory");
        }

        e_cur = __expf(bq);
        bq = bnew;
        __syncwarp();   // all lanes' pushes issued before this warp's arrives
        if (lane < 4) {
          u32 ra = mapa_u32(mb0_u + (u32)((par ^ 1) * 8), lane);
          asm volatile("mbarrier.arrive.release.cluster.shared::cluster.b64 _, [%0];"
                       :: "r"(ra) : "memory");
        }
      }
    }
    // warps 8-15 run ahead into the next step's wait + MMA
  }
}

extern "C" void kernel_launch(void* const* d_in, const int* in_sizes, int n_in,
                              void* d_out, int out_size) {
  const float* A     = (const float*)d_in[0];   // alpha_exp (H,H)
  const float* beta  = (const float*)d_in[1];   // (H,V)
  const float* gamma = (const float*)d_in[2];   // (1,H)
  const int*   ids   = (const int*)d_in[3];     // (B,T) int32
  float* out = (float*)d_out;                   // (B,H) f32

  hmm_main<<<128, NT>>>(A, beta, gamma, ids, out);
}